// round 16
// baseline (speedup 1.0000x reference)
#include <cuda_runtime.h>
#include <cuda_fp16.h>

#define NN 100000     // nodes
#define NE 1600000    // edges
#define INF 64        // input features
#define OF 40         // output features
#define NQ (OF / 4)   // 10 float-quads per row
#define NL 5          // fp16 row = 80B = 5 x uint4 -> 5 lanes per node in hops
#define NC 10000      // clusters
#define SNB ((NN + 1023) / 1024)   // 98 scan blocks (tile = 256 thr * 4 items)

// ---- scratch (device globals; no dynamic allocation allowed) ----
__device__ __align__(16) __half g_uh[NN * OF];   // fp16 feature ping
__device__ __align__(16) __half g_vh[NN * OF];   // fp16 feature pong
__device__ __align__(16) int   g_deg[NN];
__device__ __align__(16) float g_dinv[NN];
__device__ __align__(16) int   g_off[NN];
__device__ __align__(16) int   g_cur[NN];
__device__ __align__(16) int   g_csr[NE];
__device__ __align__(16) int   g_part[SNB];
__device__ __align__(16) float g_xc[NC * OF];
__device__ __align__(16) int   g_cnt[NC];

__device__ __forceinline__ void red_add_v4(float* p, float4 v) {
    asm volatile("red.global.add.v4.f32 [%0], {%1,%2,%3,%4};"
                 :: "l"(p), "f"(v.x), "f"(v.y), "f"(v.z), "f"(v.w)
                 : "memory");
}

__device__ __forceinline__ void acc8(float* a, uint4 v) {
    float2 t;
    t = __half22float2(*reinterpret_cast<__half2*>(&v.x)); a[0] += t.x; a[1] += t.y;
    t = __half22float2(*reinterpret_cast<__half2*>(&v.y)); a[2] += t.x; a[3] += t.y;
    t = __half22float2(*reinterpret_cast<__half2*>(&v.z)); a[4] += t.x; a[5] += t.y;
    t = __half22float2(*reinterpret_cast<__half2*>(&v.w)); a[6] += t.x; a[7] += t.y;
}

// zero deg/cnt only (xc zeroing moved into k_scanB, off the hist prefix)
__global__ void k_init() {
    int i = blockIdx.x * blockDim.x + threadIdx.x;
    if (i < NN) g_deg[i] = 0;
    if (i < NC) g_cnt[i] = 0;
}

__global__ void k_hist(const int* __restrict__ row, const int* __restrict__ cl) {
    int i = blockIdx.x * blockDim.x + threadIdx.x;
    if (i < NE) atomicAdd(&g_deg[__ldg(row + i)], 1);
    if (i < NN) atomicAdd(&g_cnt[__ldg(cl + i)], 1);
}

__global__ void k_dinv() {
    int i = blockIdx.x * blockDim.x + threadIdx.x;
    if (i < NN) g_dinv[i] = rsqrtf((float)(g_deg[i] + 1));
}

// Pass A: per-block exclusive offsets + block totals.
__global__ void __launch_bounds__(256) k_scanA() {
    __shared__ int warp_sums[8];
    int lane = threadIdx.x & 31, wid = threadIdx.x >> 5;
    int idx = blockIdx.x * 1024 + threadIdx.x * 4;

    int4 d = make_int4(0, 0, 0, 0);
    if (idx + 3 < NN) d = *(const int4*)(g_deg + idx);
    else {
        if (idx < NN)     d.x = g_deg[idx];
        if (idx + 1 < NN) d.y = g_deg[idx + 1];
        if (idx + 2 < NN) d.z = g_deg[idx + 2];
    }
    int s3 = d.x + d.y + d.z + d.w;

    int v = s3;
#pragma unroll
    for (int o = 1; o < 32; o <<= 1) {
        int t = __shfl_up_sync(~0u, v, o);
        if (lane >= o) v += t;
    }
    if (lane == 31) warp_sums[wid] = v;
    __syncthreads();
    if (wid == 0) {
        int w = (lane < 8) ? warp_sums[lane] : 0;
#pragma unroll
        for (int o = 1; o < 8; o <<= 1) {
            int t = __shfl_up_sync(~0u, w, o);
            if (lane >= o) w += t;
        }
        if (lane < 8) warp_sums[lane] = w;
    }
    __syncthreads();
    int excl = (v - s3) + (wid ? warp_sums[wid - 1] : 0);

    int e0 = excl, e1 = e0 + d.x, e2 = e1 + d.y, e3 = e2 + d.z;
    if (idx + 3 < NN) {
        *(int4*)(g_off + idx) = make_int4(e0, e1, e2, e3);
    } else {
        int ee[4] = {e0, e1, e2, e3};
        for (int t = 0; t < 4; t++)
            if (idx + t < NN) g_off[idx + t] = ee[t];
    }
    if (threadIdx.x == 0) g_part[blockIdx.x] = warp_sums[7];
}

// Pass B: redundant per-block base; finalize off + cur. Also zeroes g_xc
// (needed only by the hops, which come after; keeps k_init off the prefix).
__global__ void __launch_bounds__(256) k_scanB() {
    // xc zeroing: 98*256 threads * 4 float4 = 1.6MB covered
    {
        int z = (blockIdx.x * 256 + threadIdx.x) * 16;
#pragma unroll
        for (int t = 0; t < 4; t++) {
            int zz = z + t * 4;
            if (zz < NC * OF)
                *(float4*)(g_xc + zz) = make_float4(0.f, 0.f, 0.f, 0.f);
        }
    }
    __shared__ int sh_part[SNB];
    __shared__ int sh_base;
    for (int t = threadIdx.x; t < SNB; t += blockDim.x) sh_part[t] = g_part[t];
    __syncthreads();
    if (threadIdx.x == 0) {
        int base = 0;
        for (int j = 0; j < (int)blockIdx.x; j++) base += sh_part[j];
        sh_base = base;
    }
    __syncthreads();
    int base = sh_base;
    int idx = blockIdx.x * 1024 + threadIdx.x * 4;
    if (idx + 3 < NN) {
        int4 o = *(const int4*)(g_off + idx);
        o.x += base; o.y += base; o.z += base; o.w += base;
        *(int4*)(g_off + idx) = o;
        *(int4*)(g_cur + idx) = o;
    } else {
        for (int t = 0; t < 4; t++)
            if (idx + t < NN) {
                int o = g_off[idx + t] + base;
                g_off[idx + t] = o;
                g_cur[idx + t] = o;
            }
    }
}

__global__ void k_scatter(const int* __restrict__ row, const int* __restrict__ col) {
    int i = blockIdx.x * blockDim.x + threadIdx.x;
    if (i >= NE) return;
    int r = __ldg(row + i);
    int pos = atomicAdd(&g_cur[r], 1);
    g_csr[pos] = __ldg(col + i);
}

// u0 = dinv * (x @ W^T). FOUR nodes per thread x 20 outputs (half-split),
// f32x2 accumulators: 40 ull accs (80 regs), FFMA2 halves the FMA instr
// stream and each W smem read serves 4 nodes. h = tid>>7 (warp-uniform).
__global__ void __launch_bounds__(256) k_transform(const float* __restrict__ x,
                                                   const float* __restrict__ W) {
    // Wq[f*10+jj] covers outputs 4jj..4jj+3 of feature f (2 f32x2 pairs)
    __shared__ ulonglong2 Wq[INF * 10];
    for (int i = threadIdx.x; i < INF * 10; i += blockDim.x) {
        int f = i / 10, jj = i - f * 10;
        unsigned long long p0, p1;
        asm("mov.b64 %0, {%1, %2};" : "=l"(p0)
            : "f"(W[(4 * jj + 0) * INF + f]), "f"(W[(4 * jj + 1) * INF + f]));
        asm("mov.b64 %0, {%1, %2};" : "=l"(p1)
            : "f"(W[(4 * jj + 2) * INF + f]), "f"(W[(4 * jj + 3) * INF + f]));
        ulonglong2 q; q.x = p0; q.y = p1;
        Wq[i] = q;
    }
    __syncthreads();

    int t = threadIdx.x & 127;
    int h = threadIdx.x >> 7;                 // warp-uniform half
    int nb = blockIdx.x * 512 + t;            // nb <= 99967 always valid
    int n1 = nb + 128, n2 = nb + 256, n3 = nb + 384;
    bool q1 = (n1 < NN), q2 = (n2 < NN), q3 = (n3 < NN);

    unsigned long long acc[4][10];
#pragma unroll
    for (int k = 0; k < 4; k++)
#pragma unroll
        for (int m = 0; m < 10; m++) acc[k][m] = 0ull;

    const float4* xp0 = (const float4*)(x + (size_t)nb * INF);
    const float4* xp1 = (const float4*)(x + (size_t)n1 * INF);
    const float4* xp2 = (const float4*)(x + (size_t)n2 * INF);
    const float4* xp3 = (const float4*)(x + (size_t)n3 * INF);
    const float4 z4 = make_float4(0.f, 0.f, 0.f, 0.f);

#pragma unroll 1
    for (int fc = 0; fc < INF; fc += 4) {
        float4 v0 = __ldg(xp0 + fc / 4);
        float4 v1 = q1 ? __ldg(xp1 + fc / 4) : z4;
        float4 v2 = q2 ? __ldg(xp2 + fc / 4) : z4;
        float4 v3 = q3 ? __ldg(xp3 + fc / 4) : z4;
        float xs[4][4] = {{v0.x, v0.y, v0.z, v0.w}, {v1.x, v1.y, v1.z, v1.w},
                          {v2.x, v2.y, v2.z, v2.w}, {v3.x, v3.y, v3.z, v3.w}};
#pragma unroll
        for (int ff = 0; ff < 4; ff++) {
            unsigned long long xx[4];
#pragma unroll
            for (int k = 0; k < 4; k++)
                asm("mov.b64 %0, {%1, %1};" : "=l"(xx[k]) : "f"(xs[k][ff]));
            const ulonglong2* wr = &Wq[(fc + ff) * 10 + h * 5];
#pragma unroll
            for (int j = 0; j < 5; j++) {
                ulonglong2 q = wr[j];
#pragma unroll
                for (int k = 0; k < 4; k++) {
                    asm("fma.rn.f32x2 %0, %1, %2, %0;"
                        : "+l"(acc[k][2 * j]) : "l"(q.x), "l"(xx[k]));
                    asm("fma.rn.f32x2 %0, %1, %2, %0;"
                        : "+l"(acc[k][2 * j + 1]) : "l"(q.y), "l"(xx[k]));
                }
            }
        }
    }

    int nn[4] = {nb, n1, n2, n3};
    bool qq[4] = {true, q1, q2, q3};
#pragma unroll
    for (int k = 0; k < 4; k++) {
        if (!qq[k]) continue;
        float dv = g_dinv[nn[k]];
        uint2* up = (uint2*)(g_uh + (size_t)nn[k] * OF + h * 20);
#pragma unroll
        for (int j = 0; j < 5; j++) {
            float f0, f1, f2, f3;
            asm("mov.b64 {%0, %1}, %2;" : "=f"(f0), "=f"(f1) : "l"(acc[k][2 * j]));
            asm("mov.b64 {%0, %1}, %2;" : "=f"(f2), "=f"(f3) : "l"(acc[k][2 * j + 1]));
            __half2 ha = __floats2half2_rn(f0 * dv, f1 * dv);
            __half2 hb = __floats2half2_rn(f2 * dv, f3 * dv);
            uint2 st; st.x = *(unsigned*)&ha; st.y = *(unsigned*)&hb;
            up[j] = st;
        }
    }
}

// Gather hop over fp16 rows, fp32 accumulation. 5 lanes per node, one uint4
// (8 halves) each; 64 nodes per 320-thread block.
// DIR=0: g_uh -> g_vh.  DIR=1: g_vh -> g_uh.  LAST: g_uh -> cluster RED (fp32).
template <int DIR, int LAST>
__global__ void __launch_bounds__(320) k_hop(const int* __restrict__ cl) {
    int tid = threadIdx.x;
    int g = tid / NL;
    int q = tid - g * NL;
    int n = blockIdx.x * 64 + g;
    if (n >= NN) return;

    const uint4* base = (const uint4*)(DIR ? g_vh : g_uh);
    int s = g_off[n];
    int e = s + g_deg[n];

    float acc[8] = {0.f, 0.f, 0.f, 0.f, 0.f, 0.f, 0.f, 0.f};
    acc8(acc, __ldg(base + (size_t)n * NL + q));   // self loop

    int j = s;
    for (; j + 4 <= e; j += 4) {
        int c0 = __ldg(g_csr + j);
        int c1 = __ldg(g_csr + j + 1);
        int c2 = __ldg(g_csr + j + 2);
        int c3 = __ldg(g_csr + j + 3);
        uint4 a = __ldg(base + (size_t)c0 * NL + q);
        uint4 b = __ldg(base + (size_t)c1 * NL + q);
        uint4 c = __ldg(base + (size_t)c2 * NL + q);
        uint4 d = __ldg(base + (size_t)c3 * NL + q);
        acc8(acc, a); acc8(acc, b); acc8(acc, c); acc8(acc, d);
    }
    for (; j < e; j++) {
        int c0 = __ldg(g_csr + j);
        acc8(acc, __ldg(base + (size_t)c0 * NL + q));
    }

    float dv = g_dinv[n];
    float sc = LAST ? dv : dv * dv;
#pragma unroll
    for (int k = 0; k < 8; k++) acc[k] *= sc;

    if (LAST) {
        int c = __ldg(cl + n);
        float* dst = g_xc + (size_t)c * OF + q * 8;
        red_add_v4(dst, make_float4(acc[0], acc[1], acc[2], acc[3]));
        red_add_v4(dst + 4, make_float4(acc[4], acc[5], acc[6], acc[7]));
    } else {
        uint4* outp = (uint4*)(DIR ? g_uh : g_vh);
        __half2 h0 = __floats2half2_rn(acc[0], acc[1]);
        __half2 h1 = __floats2half2_rn(acc[2], acc[3]);
        __half2 h2 = __floats2half2_rn(acc[4], acc[5]);
        __half2 h3 = __floats2half2_rn(acc[6], acc[7]);
        uint4 st;
        st.x = *(unsigned*)&h0; st.y = *(unsigned*)&h1;
        st.z = *(unsigned*)&h2; st.w = *(unsigned*)&h3;
        outp[(size_t)n * NL + q] = st;
    }
}

// out[n] = xc[cluster[n]] / max(cnt,1) + b   (all fp32)
__global__ void k_out(const int* __restrict__ cl, const float* __restrict__ b,
                      float* __restrict__ out) {
    int i = blockIdx.x * blockDim.x + threadIdx.x;
    if (i >= NN * NQ) return;
    int n = i / NQ;
    int q = i - n * NQ;
    int c = __ldg(cl + n);
    float s = 1.0f / (float)max(g_cnt[c], 1);
    float4 t = ((const float4*)g_xc)[c * NQ + q];
    float4 bb = ((const float4*)b)[q];
    float4 o;
    o.x = t.x * s + bb.x;
    o.y = t.y * s + bb.y;
    o.z = t.z * s + bb.z;
    o.w = t.w * s + bb.w;
    ((float4*)out)[i] = o;
}

// side stream + events: created ONCE on the first (correctness, non-captured)
// call via magic static; work per call is identical, so determinism holds.
struct Aux {
    cudaStream_t s2;
    cudaEvent_t ev0, ev2;
    bool ok;
    Aux() {
        ok = (cudaStreamCreateWithFlags(&s2, cudaStreamNonBlocking) == cudaSuccess) &&
             (cudaEventCreateWithFlags(&ev0, cudaEventDisableTiming) == cudaSuccess) &&
             (cudaEventCreateWithFlags(&ev2, cudaEventDisableTiming) == cudaSuccess);
    }
};

extern "C" void kernel_launch(void* const* d_in, const int* in_sizes, int n_in,
                              void* d_out, int out_size) {
    const float* x = nullptr;
    const int* ei = nullptr;
    const int* cl = nullptr;
    const float* W = nullptr;
    const float* b = nullptr;
    for (int i = 0; i < n_in; i++) {
        switch (in_sizes[i]) {
            case NN * INF: x = (const float*)d_in[i]; break;
            case 2 * NE:   ei = (const int*)d_in[i]; break;
            case NN:       cl = (const int*)d_in[i]; break;
            case OF * INF: W = (const float*)d_in[i]; break;
            case OF:       b = (const float*)d_in[i]; break;
            default: break;
        }
    }
    const int* row = ei;        // targets
    const int* col = ei + NE;   // sources

    static Aux aux;             // first call is the (uncaptured) correctness run

    const int B = 256;
    k_init<<<(NN + B - 1) / B, B>>>();
    k_hist<<<(NE + B - 1) / B, B>>>(row, cl);

    const int TG = (NN + 511) / 512;
    if (aux.ok) {
        // fork AFTER hist — transform overlaps scan+scatter on legacy
        cudaEventRecord(aux.ev0, 0);
        cudaStreamWaitEvent(aux.s2, aux.ev0, 0);
        k_dinv<<<(NN + B - 1) / B, B, 0, aux.s2>>>();
        k_transform<<<TG, 256, 0, aux.s2>>>(x, W);
        cudaEventRecord(aux.ev2, aux.s2);

        k_scanA<<<SNB, 256>>>();
        k_scanB<<<SNB, 256>>>();
        k_scatter<<<(NE + B - 1) / B, B>>>(row, col);
        cudaStreamWaitEvent(0, aux.ev2, 0);   // join before hops
    } else {
        k_dinv<<<(NN + B - 1) / B, B>>>();
        k_scanA<<<SNB, 256>>>();
        k_scanB<<<SNB, 256>>>();
        k_scatter<<<(NE + B - 1) / B, B>>>(row, col);
        k_transform<<<TG, 256>>>(x, W);
    }

    const int HG = (NN + 63) / 64;
    k_hop<0, 0><<<HG, 320>>>(cl);   // uh -> vh
    k_hop<1, 0><<<HG, 320>>>(cl);   // vh -> uh
    k_hop<0, 1><<<HG, 320>>>(cl);   // uh -> cluster sums (fp32 RED)
    k_out<<<(NN * NQ + B - 1) / B, B>>>(cl, b, (float*)d_out);
}

// round 17
// speedup vs baseline: 1.0630x; 1.0630x over previous
#include <cuda_runtime.h>
#include <cuda_fp16.h>

#define NN 100000     // nodes
#define NE 1600000    // edges
#define INF 64        // input features
#define OF 40         // output features
#define NQ (OF / 4)   // 10 float-quads per row
#define NL 5          // fp16 row = 80B = 5 x uint4 -> 5 lanes per node in hops
#define NC 10000      // clusters
#define SNB ((NN + 1023) / 1024)   // 98 scan blocks (tile = 256 thr * 4 items)

// ---- scratch (device globals; no dynamic allocation allowed) ----
__device__ __align__(16) __half g_uh[NN * OF];   // fp16 feature ping
__device__ __align__(16) __half g_vh[NN * OF];   // fp16 feature pong
__device__ __align__(16) int   g_deg[NN];
__device__ __align__(16) float g_dinv[NN];
__device__ __align__(16) int   g_off[NN];
__device__ __align__(16) int   g_cur[NN];
__device__ __align__(16) int   g_csr[NE];
__device__ __align__(16) int   g_part[SNB];
__device__ __align__(16) float g_xc[NC * OF];
__device__ __align__(16) int   g_cnt[NC];

__device__ __forceinline__ void red_add_v4(float* p, float4 v) {
    asm volatile("red.global.add.v4.f32 [%0], {%1,%2,%3,%4};"
                 :: "l"(p), "f"(v.x), "f"(v.y), "f"(v.z), "f"(v.w)
                 : "memory");
}

__device__ __forceinline__ void acc8(float* a, uint4 v) {
    float2 t;
    t = __half22float2(*reinterpret_cast<__half2*>(&v.x)); a[0] += t.x; a[1] += t.y;
    t = __half22float2(*reinterpret_cast<__half2*>(&v.y)); a[2] += t.x; a[3] += t.y;
    t = __half22float2(*reinterpret_cast<__half2*>(&v.z)); a[4] += t.x; a[5] += t.y;
    t = __half22float2(*reinterpret_cast<__half2*>(&v.w)); a[6] += t.x; a[7] += t.y;
}

// zero deg/cnt/xc (kernel, not memset: must be IN the captured graph)
__global__ void k_init() {
    int i = blockIdx.x * blockDim.x + threadIdx.x;
    if (i < NN) g_deg[i] = 0;
    if (i < NC) g_cnt[i] = 0;
    if (i < NC * OF) g_xc[i] = 0.f;
}

__global__ void k_hist(const int* __restrict__ row, const int* __restrict__ cl) {
    int i = blockIdx.x * blockDim.x + threadIdx.x;
    if (i < NE) atomicAdd(&g_deg[__ldg(row + i)], 1);
    if (i < NN) atomicAdd(&g_cnt[__ldg(cl + i)], 1);
}

__global__ void k_dinv() {
    int i = blockIdx.x * blockDim.x + threadIdx.x;
    if (i < NN) g_dinv[i] = rsqrtf((float)(g_deg[i] + 1));
}

// Pass A: per-block exclusive offsets + block totals.
__global__ void __launch_bounds__(256) k_scanA() {
    __shared__ int warp_sums[8];
    int lane = threadIdx.x & 31, wid = threadIdx.x >> 5;
    int idx = blockIdx.x * 1024 + threadIdx.x * 4;

    int4 d = make_int4(0, 0, 0, 0);
    if (idx + 3 < NN) d = *(const int4*)(g_deg + idx);
    else {
        if (idx < NN)     d.x = g_deg[idx];
        if (idx + 1 < NN) d.y = g_deg[idx + 1];
        if (idx + 2 < NN) d.z = g_deg[idx + 2];
    }
    int s3 = d.x + d.y + d.z + d.w;

    int v = s3;
#pragma unroll
    for (int o = 1; o < 32; o <<= 1) {
        int t = __shfl_up_sync(~0u, v, o);
        if (lane >= o) v += t;
    }
    if (lane == 31) warp_sums[wid] = v;
    __syncthreads();
    if (wid == 0) {
        int w = (lane < 8) ? warp_sums[lane] : 0;
#pragma unroll
        for (int o = 1; o < 8; o <<= 1) {
            int t = __shfl_up_sync(~0u, w, o);
            if (lane >= o) w += t;
        }
        if (lane < 8) warp_sums[lane] = w;
    }
    __syncthreads();
    int excl = (v - s3) + (wid ? warp_sums[wid - 1] : 0);

    int e0 = excl, e1 = e0 + d.x, e2 = e1 + d.y, e3 = e2 + d.z;
    if (idx + 3 < NN) {
        *(int4*)(g_off + idx) = make_int4(e0, e1, e2, e3);
    } else {
        int ee[4] = {e0, e1, e2, e3};
        for (int t = 0; t < 4; t++)
            if (idx + t < NN) g_off[idx + t] = ee[t];
    }
    if (threadIdx.x == 0) g_part[blockIdx.x] = warp_sums[7];
}

// Pass B: redundant per-block base from the 98 partials; finalize off + cur.
__global__ void __launch_bounds__(256) k_scanB() {
    __shared__ int sh_part[SNB];
    __shared__ int sh_base;
    for (int t = threadIdx.x; t < SNB; t += blockDim.x) sh_part[t] = g_part[t];
    __syncthreads();
    if (threadIdx.x == 0) {
        int base = 0;
        for (int j = 0; j < (int)blockIdx.x; j++) base += sh_part[j];
        sh_base = base;
    }
    __syncthreads();
    int base = sh_base;
    int idx = blockIdx.x * 1024 + threadIdx.x * 4;
    if (idx + 3 < NN) {
        int4 o = *(const int4*)(g_off + idx);
        o.x += base; o.y += base; o.z += base; o.w += base;
        *(int4*)(g_off + idx) = o;
        *(int4*)(g_cur + idx) = o;
    } else {
        for (int t = 0; t < 4; t++)
            if (idx + t < NN) {
                int o = g_off[idx + t] + base;
                g_off[idx + t] = o;
                g_cur[idx + t] = o;
            }
    }
}

__global__ void k_scatter(const int* __restrict__ row, const int* __restrict__ col) {
    int i = blockIdx.x * blockDim.x + threadIdx.x;
    if (i >= NE) return;
    int r = __ldg(row + i);
    int pos = atomicAdd(&g_cur[r], 1);
    g_csr[pos] = __ldg(col + i);
}

// u0 = dinv * (x @ W^T). TWO nodes x 20 outputs (half-split) per thread,
// f32x2 accumulators: only 20 ull accs (40 regs, ~70 total) -> 100K threads,
// ~2x R15 occupancy; FFMA2 halves the FMA instr stream; each 16B W smem
// broadcast serves 2 nodes. h = tid>>7 is warp-uniform.
__global__ void __launch_bounds__(256) k_transform(const float* __restrict__ x,
                                                   const float* __restrict__ W) {
    // Wq[f*10+jj] covers outputs 4jj..4jj+3 of feature f (2 f32x2 pairs)
    __shared__ ulonglong2 Wq[INF * 10];
    for (int i = threadIdx.x; i < INF * 10; i += blockDim.x) {
        int f = i / 10, jj = i - f * 10;
        unsigned long long p0, p1;
        asm("mov.b64 %0, {%1, %2};" : "=l"(p0)
            : "f"(W[(4 * jj + 0) * INF + f]), "f"(W[(4 * jj + 1) * INF + f]));
        asm("mov.b64 %0, {%1, %2};" : "=l"(p1)
            : "f"(W[(4 * jj + 2) * INF + f]), "f"(W[(4 * jj + 3) * INF + f]));
        ulonglong2 q; q.x = p0; q.y = p1;
        Wq[i] = q;
    }
    __syncthreads();

    int t = threadIdx.x & 127;
    int h = threadIdx.x >> 7;                 // warp-uniform half (0/1)
    int n0 = blockIdx.x * 256 + t;            // max 99967 < NN, always valid
    int n1 = n0 + 128;
    bool q1 = (n1 < NN);

    unsigned long long a0[10], a1[10];        // 20 ull = 40 regs
#pragma unroll
    for (int m = 0; m < 10; m++) { a0[m] = 0ull; a1[m] = 0ull; }

    const float4* xp0 = (const float4*)(x + (size_t)n0 * INF);
    const float4* xp1 = (const float4*)(x + (size_t)n1 * INF);
    const float4 z4 = make_float4(0.f, 0.f, 0.f, 0.f);

#pragma unroll 1
    for (int fc = 0; fc < INF; fc += 4) {
        float4 v0 = __ldg(xp0 + fc / 4);
        float4 v1 = q1 ? __ldg(xp1 + fc / 4) : z4;
        float xs0[4] = {v0.x, v0.y, v0.z, v0.w};
        float xs1[4] = {v1.x, v1.y, v1.z, v1.w};
#pragma unroll
        for (int ff = 0; ff < 4; ff++) {
            unsigned long long x0, x1;
            asm("mov.b64 %0, {%1, %1};" : "=l"(x0) : "f"(xs0[ff]));
            asm("mov.b64 %0, {%1, %1};" : "=l"(x1) : "f"(xs1[ff]));
            const ulonglong2* wr = &Wq[(fc + ff) * 10 + h * 5];
#pragma unroll
            for (int j = 0; j < 5; j++) {
                ulonglong2 q = wr[j];
                asm("fma.rn.f32x2 %0, %1, %2, %0;" : "+l"(a0[2 * j]) : "l"(q.x), "l"(x0));
                asm("fma.rn.f32x2 %0, %1, %2, %0;" : "+l"(a0[2 * j + 1]) : "l"(q.y), "l"(x0));
                asm("fma.rn.f32x2 %0, %1, %2, %0;" : "+l"(a1[2 * j]) : "l"(q.x), "l"(x1));
                asm("fma.rn.f32x2 %0, %1, %2, %0;" : "+l"(a1[2 * j + 1]) : "l"(q.y), "l"(x1));
            }
        }
    }

    {
        float dv = g_dinv[n0];
        uint2* up = (uint2*)(g_uh + (size_t)n0 * OF + h * 20);
#pragma unroll
        for (int j = 0; j < 5; j++) {
            float f0, f1, f2, f3;
            asm("mov.b64 {%0, %1}, %2;" : "=f"(f0), "=f"(f1) : "l"(a0[2 * j]));
            asm("mov.b64 {%0, %1}, %2;" : "=f"(f2), "=f"(f3) : "l"(a0[2 * j + 1]));
            __half2 ha = __floats2half2_rn(f0 * dv, f1 * dv);
            __half2 hb = __floats2half2_rn(f2 * dv, f3 * dv);
            uint2 st; st.x = *(unsigned*)&ha; st.y = *(unsigned*)&hb;
            up[j] = st;
        }
    }
    if (q1) {
        float dv = g_dinv[n1];
        uint2* up = (uint2*)(g_uh + (size_t)n1 * OF + h * 20);
#pragma unroll
        for (int j = 0; j < 5; j++) {
            float f0, f1, f2, f3;
            asm("mov.b64 {%0, %1}, %2;" : "=f"(f0), "=f"(f1) : "l"(a1[2 * j]));
            asm("mov.b64 {%0, %1}, %2;" : "=f"(f2), "=f"(f3) : "l"(a1[2 * j + 1]));
            __half2 ha = __floats2half2_rn(f0 * dv, f1 * dv);
            __half2 hb = __floats2half2_rn(f2 * dv, f3 * dv);
            uint2 st; st.x = *(unsigned*)&ha; st.y = *(unsigned*)&hb;
            up[j] = st;
        }
    }
}

// Gather hop over fp16 rows, fp32 accumulation. 5 lanes per node, one uint4
// (8 halves) each; 64 nodes per 320-thread block.
// DIR=0: g_uh -> g_vh.  DIR=1: g_vh -> g_uh.  LAST: g_uh -> cluster RED (fp32).
template <int DIR, int LAST>
__global__ void __launch_bounds__(320) k_hop(const int* __restrict__ cl) {
    int tid = threadIdx.x;
    int g = tid / NL;
    int q = tid - g * NL;
    int n = blockIdx.x * 64 + g;
    if (n >= NN) return;

    const uint4* base = (const uint4*)(DIR ? g_vh : g_uh);
    int s = g_off[n];
    int e = s + g_deg[n];

    float acc[8] = {0.f, 0.f, 0.f, 0.f, 0.f, 0.f, 0.f, 0.f};
    acc8(acc, __ldg(base + (size_t)n * NL + q));   // self loop

    int j = s;
    for (; j + 4 <= e; j += 4) {
        int c0 = __ldg(g_csr + j);
        int c1 = __ldg(g_csr + j + 1);
        int c2 = __ldg(g_csr + j + 2);
        int c3 = __ldg(g_csr + j + 3);
        uint4 a = __ldg(base + (size_t)c0 * NL + q);
        uint4 b = __ldg(base + (size_t)c1 * NL + q);
        uint4 c = __ldg(base + (size_t)c2 * NL + q);
        uint4 d = __ldg(base + (size_t)c3 * NL + q);
        acc8(acc, a); acc8(acc, b); acc8(acc, c); acc8(acc, d);
    }
    for (; j < e; j++) {
        int c0 = __ldg(g_csr + j);
        acc8(acc, __ldg(base + (size_t)c0 * NL + q));
    }

    float dv = g_dinv[n];
    float sc = LAST ? dv : dv * dv;
#pragma unroll
    for (int k = 0; k < 8; k++) acc[k] *= sc;

    if (LAST) {
        int c = __ldg(cl + n);
        float* dst = g_xc + (size_t)c * OF + q * 8;
        red_add_v4(dst, make_float4(acc[0], acc[1], acc[2], acc[3]));
        red_add_v4(dst + 4, make_float4(acc[4], acc[5], acc[6], acc[7]));
    } else {
        uint4* outp = (uint4*)(DIR ? g_uh : g_vh);
        __half2 h0 = __floats2half2_rn(acc[0], acc[1]);
        __half2 h1 = __floats2half2_rn(acc[2], acc[3]);
        __half2 h2 = __floats2half2_rn(acc[4], acc[5]);
        __half2 h3 = __floats2half2_rn(acc[6], acc[7]);
        uint4 st;
        st.x = *(unsigned*)&h0; st.y = *(unsigned*)&h1;
        st.z = *(unsigned*)&h2; st.w = *(unsigned*)&h3;
        outp[(size_t)n * NL + q] = st;
    }
}

// out[n] = xc[cluster[n]] / max(cnt,1) + b   (all fp32)
__global__ void k_out(const int* __restrict__ cl, const float* __restrict__ b,
                      float* __restrict__ out) {
    int i = blockIdx.x * blockDim.x + threadIdx.x;
    if (i >= NN * NQ) return;
    int n = i / NQ;
    int q = i - n * NQ;
    int c = __ldg(cl + n);
    float s = 1.0f / (float)max(g_cnt[c], 1);
    float4 t = ((const float4*)g_xc)[c * NQ + q];
    float4 bb = ((const float4*)b)[q];
    float4 o;
    o.x = t.x * s + bb.x;
    o.y = t.y * s + bb.y;
    o.z = t.z * s + bb.z;
    o.w = t.w * s + bb.w;
    ((float4*)out)[i] = o;
}

// side stream + events: created ONCE on the first (correctness, non-captured)
// call via magic static; work per call is identical, so determinism holds.
struct Aux {
    cudaStream_t s2;
    cudaEvent_t ev0, ev2;
    bool ok;
    Aux() {
        ok = (cudaStreamCreateWithFlags(&s2, cudaStreamNonBlocking) == cudaSuccess) &&
             (cudaEventCreateWithFlags(&ev0, cudaEventDisableTiming) == cudaSuccess) &&
             (cudaEventCreateWithFlags(&ev2, cudaEventDisableTiming) == cudaSuccess);
    }
};

extern "C" void kernel_launch(void* const* d_in, const int* in_sizes, int n_in,
                              void* d_out, int out_size) {
    const float* x = nullptr;
    const int* ei = nullptr;
    const int* cl = nullptr;
    const float* W = nullptr;
    const float* b = nullptr;
    for (int i = 0; i < n_in; i++) {
        switch (in_sizes[i]) {
            case NN * INF: x = (const float*)d_in[i]; break;
            case 2 * NE:   ei = (const int*)d_in[i]; break;
            case NN:       cl = (const int*)d_in[i]; break;
            case OF * INF: W = (const float*)d_in[i]; break;
            case OF:       b = (const float*)d_in[i]; break;
            default: break;
        }
    }
    const int* row = ei;        // targets
    const int* col = ei + NE;   // sources

    static Aux aux;             // first call is the (uncaptured) correctness run

    const int B = 256;
    k_init<<<(NC * OF + B - 1) / B, B>>>();
    k_hist<<<(NE + B - 1) / B, B>>>(row, cl);

    const int TG = (NN + 255) / 256;
    if (aux.ok) {
        // fork AFTER hist — transform overlaps scan+scatter on legacy
        cudaEventRecord(aux.ev0, 0);
        cudaStreamWaitEvent(aux.s2, aux.ev0, 0);
        k_dinv<<<(NN + B - 1) / B, B, 0, aux.s2>>>();
        k_transform<<<TG, 256, 0, aux.s2>>>(x, W);
        cudaEventRecord(aux.ev2, aux.s2);

        k_scanA<<<SNB, 256>>>();
        k_scanB<<<SNB, 256>>>();
        k_scatter<<<(NE + B - 1) / B, B>>>(row, col);
        cudaStreamWaitEvent(0, aux.ev2, 0);   // join before hops
    } else {
        k_dinv<<<(NN + B - 1) / B, B>>>();
        k_scanA<<<SNB, 256>>>();
        k_scanB<<<SNB, 256>>>();
        k_scatter<<<(NE + B - 1) / B, B>>>(row, col);
        k_transform<<<TG, 256>>>(x, W);
    }

    const int HG = (NN + 63) / 64;
    k_hop<0, 0><<<HG, 320>>>(cl);   // uh -> vh
    k_hop<1, 0><<<HG, 320>>>(cl);   // vh -> uh
    k_hop<0, 1><<<HG, 320>>>(cl);   // uh -> cluster sums (fp32 RED)
    k_out<<<(NN * NQ + B - 1) / B, B>>>(cl, b, (float*)d_out);
}